// round 6
// baseline (speedup 1.0000x reference)
#include <cuda_runtime.h>
#include <cuda_bf16.h>
#include <cstdint>
#include <cstring>

// Problem dims
#define BDIM 16384
#define KDIM 4096
#define NDIM 512

// Binarized weight, u8 {0,1}, [NDIM, KDIM] row-major. 2 MB.
__device__ __align__(256) uint8_t g_wbin[(size_t)NDIM * KDIM];
// Quantized x, u8 = rn(x*255), [BDIM, KDIM]. 64 MB.
__device__ __align__(256) uint8_t g_xq[(size_t)BDIM * KDIM];

// ---------------------------------------------------------------------------
// helpers
// ---------------------------------------------------------------------------
__device__ __forceinline__ uint32_t smem_u32(const void* p) {
    uint32_t a;
    asm("{ .reg .u64 t; cvta.to.shared.u64 t, %1; cvt.u32.u64 %0, t; }"
        : "=r"(a) : "l"(p));
    return a;
}

#define SWZ(off) ((uint32_t)(off) ^ ((((uint32_t)(off)) >> 3) & 0x70))

#define LDSM_X4(r0, r1, r2, r3, addr) \
    asm volatile("ldmatrix.sync.aligned.m8n8.x4.shared.b16 {%0,%1,%2,%3}, [%4];" \
        : "=r"(r0), "=r"(r1), "=r"(r2), "=r"(r3) : "r"(addr))

// u8 x u8 -> s32, m16n8k32
#define IMMA16832(d, a, b0, b1) \
    asm volatile("mma.sync.aligned.m16n8k32.row.col.s32.u8.u8.s32 " \
        "{%0,%1,%2,%3}, {%4,%5,%6,%7}, {%8,%9}, {%0,%1,%2,%3};" \
        : "+r"((d)[0]), "+r"((d)[1]), "+r"((d)[2]), "+r"((d)[3]) \
        : "r"((a)[0]), "r"((a)[1]), "r"((a)[2]), "r"((a)[3]), "r"(b0), "r"(b1))

#define CP_ASYNC16(dst, src) \
    asm volatile("cp.async.cg.shared.global [%0], [%1], 16;" \
        :: "r"(dst), "l"(src) : "memory")
#define CP_COMMIT() asm volatile("cp.async.commit_group;" ::: "memory")
#define CP_WAIT2()  asm volatile("cp.async.wait_group 2;" ::: "memory")

// ---------------------------------------------------------------------------
// Kernel 1: binarize weight -> u8 {0,1}. 16 elems/thread.
// ---------------------------------------------------------------------------
__global__ void __launch_bounds__(256) binarize_kernel(
    const float* __restrict__ w, const float* __restrict__ u) {
    int i = blockIdx.x * 256 + threadIdx.x;   // 16 elems each
    const float4* w4 = reinterpret_cast<const float4*>(w) + (size_t)i * 4;
    const float4* u4 = reinterpret_cast<const float4*>(u) + (size_t)i * 4;
    uint32_t o[4];
    #pragma unroll
    for (int j = 0; j < 4; j++) {
        float4 wv = w4[j], uv = u4[j];
        o[j] = (uv.x < wv.x ? 0x01u : 0u) | (uv.y < wv.y ? 0x0100u : 0u) |
               (uv.z < wv.z ? 0x010000u : 0u) | (uv.w < wv.w ? 0x01000000u : 0u);
    }
    reinterpret_cast<uint4*>(g_wbin)[i] = make_uint4(o[0], o[1], o[2], o[3]);
}

// ---------------------------------------------------------------------------
// Kernel 2: quantize x fp32 -> u8 (q = rn(x*255)). Streaming, ~50us.
// ---------------------------------------------------------------------------
__global__ void __launch_bounds__(256) convert_x_kernel(const float* __restrict__ x) {
    int i = blockIdx.x * 256 + threadIdx.x;   // 16 elems each
    const float4* p = reinterpret_cast<const float4*>(x) + (size_t)i * 4;
    uint32_t o[4];
    #pragma unroll
    for (int j = 0; j < 4; j++) {
        float4 f = p[j];
        uint32_t b0 = (uint32_t)__float2int_rn(f.x * 255.f);
        uint32_t b1 = (uint32_t)__float2int_rn(f.y * 255.f);
        uint32_t b2 = (uint32_t)__float2int_rn(f.z * 255.f);
        uint32_t b3 = (uint32_t)__float2int_rn(f.w * 255.f);
        o[j] = b0 | (b1 << 8) | (b2 << 16) | (b3 << 24);
    }
    reinterpret_cast<uint4*>(g_xq)[i] = make_uint4(o[0], o[1], o[2], o[3]);
}

// ---------------------------------------------------------------------------
// Kernel 3: u8 IMMA GEMM, all-cp.async, 4-stage pipeline.
//   out[16384, 512] = (g_xq @ g_wbin^T) * (1/255)   (s32 accum = exact)
//   BM=256, BN=128, BK=128 (bytes). 256 threads = 8 warps (4x2), warp 64x64.
//   128B SW128 row holds K=128 u8, NC=32, each ks covers 32 k via m16n8k32.
//   NOTE (R5 bug): ldmatrix.x4 register order with this addressing is
//   ALREADY the IMMA A-fragment order (r0=rows0-7/k0-15, r1=rows8-15/k0-15,
//   r2=rows0-7/k16-31, r3=rows8-15/k16-31). No permutation.
// ---------------------------------------------------------------------------
static constexpr int BM = 256, BN = 128, BK = 128;
static constexpr int NC = KDIM / BK;              // 32
static constexpr int THREADS = 256;
static constexpr int STAGES = 4;

static constexpr int A_ST  = BM * 128;            // 32 KB
static constexpr int B_ST  = BN * 128;            // 16 KB
static constexpr int STAGE = A_ST + B_ST;         // 48 KB
static constexpr int SMEM_TOTAL = STAGES * STAGE; // 192 KB

// cp.async both tiles for chunk c into stage buffer.
__device__ __forceinline__ void cpAB(uint32_t sbase, int c, int m0, int n0, int tid) {
    const uint8_t* ag = g_xq + (size_t)m0 * KDIM + (size_t)c * BK;
    #pragma unroll
    for (int it = 0; it < 8; it++) {              // 2048 tasks: 256 rows x 8 segs
        const int task = tid + it * THREADS;
        const int r = task >> 3;
        const int t = task & 7;
        CP_ASYNC16(sbase + SWZ(r * 128 + t * 16),
                   ag + (size_t)r * KDIM + t * 16);
    }
    const uint8_t* bg = g_wbin + (size_t)n0 * KDIM + (size_t)c * BK;
    const uint32_t bbase = sbase + A_ST;
    #pragma unroll
    for (int it = 0; it < 4; it++) {              // 1024 tasks: 128 rows x 8 segs
        const int task = tid + it * THREADS;
        const int r = task >> 3;
        const int t = task & 7;
        CP_ASYNC16(bbase + SWZ(r * 128 + t * 16),
                   bg + (size_t)r * KDIM + t * 16);
    }
}

__global__ void __launch_bounds__(THREADS, 1) binlin_gemm(float* __restrict__ out) {
    extern __shared__ char smem[];
    const uint32_t smem_base = smem_u32(smem);
    const int tid = threadIdx.x;
    const int wid = tid >> 5;
    const int lid = tid & 31;

    const int n0 = blockIdx.x * BN;               // 0..384 step 128
    const int m0 = blockIdx.y * BM;               // 0..16128 step 256

    const int warp_m = wid >> 1;                  // 0..3  (64 rows each)
    const int warp_n = wid & 1;                   // 0..1  (64 cols each)

    // per-lane ldmatrix address components (16B segment units)
    const int lr = lid & 7;
    const int lg = lid >> 3;
    const int a_row  = warp_m * 64 + (lg & 1) * 8 + lr;   // + mf*16
    const int a_colb = (lg >> 1) * 16;                    // + ks*32 (bytes)
    const int b_row  = warp_n * 64 + (lg >> 1) * 8 + lr;  // + nf2*16
    const int b_colb = (lg & 1) * 16;                     // + ks*32 (bytes)

    int acc[4][8][4];
    #pragma unroll
    for (int i = 0; i < 4; i++)
        #pragma unroll
        for (int j = 0; j < 8; j++)
            #pragma unroll
            for (int k = 0; k < 4; k++) acc[i][j][k] = 0;

    // ---- prologue: prefetch stages 0..2 ----
    #pragma unroll
    for (int s = 0; s < STAGES - 1; s++) {
        cpAB(smem_base + s * STAGE, s, m0, n0, tid);
        CP_COMMIT();
    }

    // ---- main loop ----
    for (int c = 0; c < NC; c++) {
        CP_WAIT2();            // 3 groups pending -> oldest (chunk c) complete
        __syncthreads();       // visibility + stage (c+3)&3 free of readers

        if (c + STAGES - 1 < NC)
            cpAB(smem_base + ((c + STAGES - 1) & 3) * STAGE, c + STAGES - 1, m0, n0, tid);
        CP_COMMIT();           // keep group count in lockstep (may be empty)

        const uint32_t abase = smem_base + (c & 3) * STAGE;
        const uint32_t bbase = abase + A_ST;

        #pragma unroll
        for (int ks = 0; ks < 4; ks++) {          // 4 x k32 = 128 k-elems
            uint32_t a[4][4];
            #pragma unroll
            for (int mf = 0; mf < 4; mf++) {
                const uint32_t addr = abase +
                    SWZ((a_row + mf * 16) * 128 + ks * 32 + a_colb);
                LDSM_X4(a[mf][0], a[mf][1], a[mf][2], a[mf][3], addr);
            }
            uint32_t b[4][4];
            #pragma unroll
            for (int nf2 = 0; nf2 < 4; nf2++) {
                const uint32_t addr = bbase +
                    SWZ((b_row + nf2 * 16) * 128 + ks * 32 + b_colb);
                LDSM_X4(b[nf2][0], b[nf2][1], b[nf2][2], b[nf2][3], addr);
            }
            #pragma unroll
            for (int mf = 0; mf < 4; mf++) {
                #pragma unroll
                for (int nf = 0; nf < 8; nf++) {
                    // b-frag: even nf -> regs 0,1 (n0-7); odd nf -> regs 2,3 (n8-15)
                    IMMA16832(acc[mf][nf], a[mf],
                              b[nf >> 1][(nf & 1) * 2 + 0],
                              b[nf >> 1][(nf & 1) * 2 + 1]);
                }
            }
        }
    }

    // ---- epilogue: s32 -> f32 * (1/255) -> gmem ----
    const float s = 1.0f / 255.0f;
    const int er = lid >> 2;          // 0..7
    const int ec = (lid & 3) * 2;     // 0,2,4,6
    #pragma unroll
    for (int mf = 0; mf < 4; mf++) {
        #pragma unroll
        for (int nf = 0; nf < 8; nf++) {
            const int m = m0 + warp_m * 64 + mf * 16 + er;
            const int n = n0 + warp_n * 64 + nf * 8 + ec;
            float2 v0 = make_float2((float)acc[mf][nf][0] * s, (float)acc[mf][nf][1] * s);
            float2 v1 = make_float2((float)acc[mf][nf][2] * s, (float)acc[mf][nf][3] * s);
            *reinterpret_cast<float2*>(out + (size_t)m * NDIM + n)       = v0;
            *reinterpret_cast<float2*>(out + (size_t)(m + 8) * NDIM + n) = v1;
        }
    }
}

// ---------------------------------------------------------------------------
// Launch
// ---------------------------------------------------------------------------
extern "C" void kernel_launch(void* const* d_in, const int* in_sizes, int n_in,
                              void* d_out, int out_size) {
    const float* x = (const float*)d_in[0];   // [16384, 4096]
    const float* w = (const float*)d_in[1];   // [512, 4096] bernoulli probs
    const float* u = (const float*)d_in[2];   // [512, 4096] uniform sample
    float* out = (float*)d_out;               // [16384, 512]

    cudaFuncSetAttribute(binlin_gemm,
                         cudaFuncAttributeMaxDynamicSharedMemorySize, SMEM_TOTAL);

    binarize_kernel<<<(NDIM * KDIM) / (256 * 16), 256>>>(w, u);
    convert_x_kernel<<<((size_t)BDIM * KDIM) / (256 * 16), 256>>>(x);
    dim3 grid(NDIM / BN, BDIM / BM);          // (4, 64) = 256 CTAs
    binlin_gemm<<<grid, THREADS, SMEM_TOTAL>>>(out);
}

// round 7
// speedup vs baseline: 2.5067x; 2.5067x over previous
#include <cuda_runtime.h>
#include <cuda_bf16.h>
#include <cstdint>
#include <cstring>

// Problem dims
#define BDIM 16384
#define KDIM 4096
#define NDIM 512

// Binarized weight, bf16 {0,1}, [NDIM, KDIM] row-major (K-contiguous). 4 MB.
__device__ __align__(256) __nv_bfloat16 g_wbin[(size_t)NDIM * KDIM];
// Pre-converted x, bf16, [BDIM, KDIM]. 128 MB.
__device__ __align__(256) __nv_bfloat16 g_xbf[(size_t)BDIM * KDIM];

// ---------------------------------------------------------------------------
// helpers
// ---------------------------------------------------------------------------
__device__ __forceinline__ uint32_t smem_u32(const void* p) {
    uint32_t a;
    asm("{ .reg .u64 t; cvta.to.shared.u64 t, %1; cvt.u32.u64 %0, t; }"
        : "=r"(a) : "l"(p));
    return a;
}

#define SWZ(off) ((uint32_t)(off) ^ ((((uint32_t)(off)) >> 3) & 0x70))

#define LDSM_X4(r0, r1, r2, r3, addr) \
    asm volatile("ldmatrix.sync.aligned.m8n8.x4.shared.b16 {%0,%1,%2,%3}, [%4];" \
        : "=r"(r0), "=r"(r1), "=r"(r2), "=r"(r3) : "r"(addr))

#define MMA16816(d, a, b0, b1) \
    asm volatile("mma.sync.aligned.m16n8k16.row.col.f32.bf16.bf16.f32 " \
        "{%0,%1,%2,%3}, {%4,%5,%6,%7}, {%8,%9}, {%0,%1,%2,%3};" \
        : "+f"((d)[0]), "+f"((d)[1]), "+f"((d)[2]), "+f"((d)[3]) \
        : "r"((a)[0]), "r"((a)[1]), "r"((a)[2]), "r"((a)[3]), "r"(b0), "r"(b1))

#define CP_ASYNC16(dst, src) \
    asm volatile("cp.async.cg.shared.global [%0], [%1], 16;" \
        :: "r"(dst), "l"(src) : "memory")
#define CP_COMMIT() asm volatile("cp.async.commit_group;" ::: "memory")
#define CP_WAIT2()  asm volatile("cp.async.wait_group 2;" ::: "memory")

__device__ __forceinline__ uint32_t pack_bf16x2(float lo, float hi) {
    __nv_bfloat162 h = __floats2bfloat162_rn(lo, hi);
    uint32_t r;
    memcpy(&r, &h, 4);
    return r;
}

// ---------------------------------------------------------------------------
// Kernel 1: binarize weight -> bf16 {0,1}. Pure bit select, no float math.
// ---------------------------------------------------------------------------
__global__ void __launch_bounds__(256) binarize_kernel(
    const float* __restrict__ w, const float* __restrict__ u) {
    int i = blockIdx.x * 256 + threadIdx.x;   // 8 elems each
    const float4* w4 = reinterpret_cast<const float4*>(w) + (size_t)i * 2;
    const float4* u4 = reinterpret_cast<const float4*>(u) + (size_t)i * 2;
    float4 wa = w4[0], wb = w4[1];
    float4 ua = u4[0], ub = u4[1];
    // bf16(1.0f) = 0x3F80
    uint32_t o0 = (ua.x < wa.x ? 0x00003F80u : 0u) | (ua.y < wa.y ? 0x3F800000u : 0u);
    uint32_t o1 = (ua.z < wa.z ? 0x00003F80u : 0u) | (ua.w < wa.w ? 0x3F800000u : 0u);
    uint32_t o2 = (ub.x < wb.x ? 0x00003F80u : 0u) | (ub.y < wb.y ? 0x3F800000u : 0u);
    uint32_t o3 = (ub.z < wb.z ? 0x00003F80u : 0u) | (ub.w < wb.w ? 0x3F800000u : 0u);
    reinterpret_cast<uint4*>(g_wbin)[i] = make_uint4(o0, o1, o2, o3);
}

// ---------------------------------------------------------------------------
// Kernel 2: convert x fp32 -> bf16 (streaming, DRAM-bound).
// ---------------------------------------------------------------------------
__global__ void __launch_bounds__(256) convert_x_kernel(const float* __restrict__ x) {
    int i = blockIdx.x * 256 + threadIdx.x;   // 8 elems each
    const float4* p = reinterpret_cast<const float4*>(x) + (size_t)i * 2;
    float4 f0 = p[0], f1 = p[1];
    uint4 o;
    o.x = pack_bf16x2(f0.x, f0.y);
    o.y = pack_bf16x2(f0.z, f0.w);
    o.z = pack_bf16x2(f1.x, f1.y);
    o.w = pack_bf16x2(f1.z, f1.w);
    reinterpret_cast<uint4*>(g_xbf)[i] = o;
}

// ---------------------------------------------------------------------------
// Kernel 3: bf16 mma.sync GEMM, all-cp.async, 4-stage pipeline,
//           ks-level fragment double-buffering (new in R7).
//   out[16384, 512] = g_xbf[16384, 4096] @ g_wbin[512, 4096]^T
//   BM=256, BN=128, BK=64. 256 threads = 8 warps (4 x 2), warp tile 64x64.
//   (R6: legacy u8 IMMA is ~3x SLOWER than HMMA on sm_103 -> bf16 it is.)
// ---------------------------------------------------------------------------
static constexpr int BM = 256, BN = 128, BK = 64;
static constexpr int NC = KDIM / BK;              // 64
static constexpr int THREADS = 256;
static constexpr int STAGES = 4;

static constexpr int A_ST  = BM * 128;            // 32 KB
static constexpr int B_ST  = BN * 128;            // 16 KB
static constexpr int STAGE = A_ST + B_ST;         // 48 KB
static constexpr int SMEM_TOTAL = STAGES * STAGE; // 192 KB

// cp.async both tiles for chunk c into stage buffer.
__device__ __forceinline__ void cpAB(uint32_t sbase, int c, int m0, int n0, int tid) {
    const __nv_bfloat16* ag = g_xbf + (size_t)m0 * KDIM + (size_t)c * BK;
    #pragma unroll
    for (int it = 0; it < 8; it++) {              // 2048 tasks: 256 rows x 8 segs
        const int task = tid + it * THREADS;
        const int r = task >> 3;
        const int t = task & 7;
        CP_ASYNC16(sbase + SWZ(r * 128 + t * 16),
                   ag + (size_t)r * KDIM + t * 8);
    }
    const __nv_bfloat16* bg = g_wbin + (size_t)n0 * KDIM + (size_t)c * BK;
    const uint32_t bbase = sbase + A_ST;
    #pragma unroll
    for (int it = 0; it < 4; it++) {              // 1024 tasks: 128 rows x 8 segs
        const int task = tid + it * THREADS;
        const int r = task >> 3;
        const int t = task & 7;
        CP_ASYNC16(bbase + SWZ(r * 128 + t * 16),
                   bg + (size_t)r * KDIM + t * 8);
    }
}

__global__ void __launch_bounds__(THREADS, 1) binlin_gemm(float* __restrict__ out) {
    extern __shared__ char smem[];
    const uint32_t smem_base = smem_u32(smem);
    const int tid = threadIdx.x;
    const int wid = tid >> 5;
    const int lid = tid & 31;

    const int n0 = blockIdx.x * BN;               // 0..384 step 128
    const int m0 = blockIdx.y * BM;               // 0..16128 step 256

    const int warp_m = wid >> 1;                  // 0..3  (64 rows each)
    const int warp_n = wid & 1;                   // 0..1  (64 cols each)

    // per-lane ldmatrix address components
    const int lr = lid & 7;
    const int lg = lid >> 3;
    const int a_row  = warp_m * 64 + (lg & 1) * 8 + lr;   // + mf*16
    const int a_colb = (lg >> 1) * 16;                    // + ks*32
    const int b_row  = warp_n * 64 + (lg >> 1) * 8 + lr;  // + nf2*16
    const int b_colb = (lg & 1) * 16;                     // + ks*32

    float acc[4][8][4];
    #pragma unroll
    for (int i = 0; i < 4; i++)
        #pragma unroll
        for (int j = 0; j < 8; j++)
            #pragma unroll
            for (int k = 0; k < 4; k++) acc[i][j][k] = 0.f;

    // fragment double buffers (ks-level pipeline)
    uint32_t a[2][4][4];
    uint32_t b[2][4][4];

    // ---- prologue: prefetch stages 0..2 ----
    #pragma unroll
    for (int s = 0; s < STAGES - 1; s++) {
        cpAB(smem_base + s * STAGE, s, m0, n0, tid);
        CP_COMMIT();
    }

    // ---- main loop ----
    for (int c = 0; c < NC; c++) {
        CP_WAIT2();            // 3 groups pending -> oldest (chunk c) complete
        __syncthreads();       // visibility + stage (c+3)&3 free of readers

        if (c + STAGES - 1 < NC)
            cpAB(smem_base + ((c + STAGES - 1) & 3) * STAGE, c + STAGES - 1, m0, n0, tid);
        CP_COMMIT();           // keep group count in lockstep (may be empty)

        const uint32_t abase = smem_base + (c & 3) * STAGE;
        const uint32_t bbase = abase + A_ST;

        // ks=0 fragments
        #pragma unroll
        for (int mf = 0; mf < 4; mf++) {
            const uint32_t addr = abase + SWZ((a_row + mf * 16) * 128 + a_colb);
            LDSM_X4(a[0][mf][0], a[0][mf][1], a[0][mf][2], a[0][mf][3], addr);
        }
        #pragma unroll
        for (int nf2 = 0; nf2 < 4; nf2++) {
            const uint32_t addr = bbase + SWZ((b_row + nf2 * 16) * 128 + b_colb);
            LDSM_X4(b[0][nf2][0], b[0][nf2][1], b[0][nf2][2], b[0][nf2][3], addr);
        }

        #pragma unroll
        for (int ks = 0; ks < 4; ks++) {
            const int cur = ks & 1, nxt = cur ^ 1;
            // prefetch ks+1 fragments (overlaps with MMAs below)
            if (ks < 3) {
                #pragma unroll
                for (int mf = 0; mf < 4; mf++) {
                    const uint32_t addr = abase +
                        SWZ((a_row + mf * 16) * 128 + (ks + 1) * 32 + a_colb);
                    LDSM_X4(a[nxt][mf][0], a[nxt][mf][1], a[nxt][mf][2], a[nxt][mf][3], addr);
                }
                #pragma unroll
                for (int nf2 = 0; nf2 < 4; nf2++) {
                    const uint32_t addr = bbase +
                        SWZ((b_row + nf2 * 16) * 128 + (ks + 1) * 32 + b_colb);
                    LDSM_X4(b[nxt][nf2][0], b[nxt][nf2][1], b[nxt][nf2][2], b[nxt][nf2][3], addr);
                }
            }
            #pragma unroll
            for (int mf = 0; mf < 4; mf++) {
                #pragma unroll
                for (int nf = 0; nf < 8; nf++) {
                    MMA16816(acc[mf][nf], a[cur][mf],
                             b[cur][nf >> 1][(nf & 1) * 2 + 0],
                             b[cur][nf >> 1][(nf & 1) * 2 + 1]);
                }
            }
        }
    }

    // ---- epilogue: fragments -> gmem ----
    const int er = lid >> 2;          // 0..7
    const int ec = (lid & 3) * 2;     // 0,2,4,6
    #pragma unroll
    for (int mf = 0; mf < 4; mf++) {
        #pragma unroll
        for (int nf = 0; nf < 8; nf++) {
            const int m = m0 + warp_m * 64 + mf * 16 + er;
            const int n = n0 + warp_n * 64 + nf * 8 + ec;
            float2 v0 = make_float2(acc[mf][nf][0], acc[mf][nf][1]);
            float2 v1 = make_float2(acc[mf][nf][2], acc[mf][nf][3]);
            *reinterpret_cast<float2*>(out + (size_t)m * NDIM + n)       = v0;
            *reinterpret_cast<float2*>(out + (size_t)(m + 8) * NDIM + n) = v1;
        }
    }
}

// ---------------------------------------------------------------------------
// Launch
// ---------------------------------------------------------------------------
extern "C" void kernel_launch(void* const* d_in, const int* in_sizes, int n_in,
                              void* d_out, int out_size) {
    const float* x = (const float*)d_in[0];   // [16384, 4096]
    const float* w = (const float*)d_in[1];   // [512, 4096] bernoulli probs
    const float* u = (const float*)d_in[2];   // [512, 4096] uniform sample
    float* out = (float*)d_out;               // [16384, 512]

    cudaFuncSetAttribute(binlin_gemm,
                         cudaFuncAttributeMaxDynamicSharedMemorySize, SMEM_TOTAL);

    binarize_kernel<<<(NDIM * KDIM) / (256 * 8), 256>>>(w, u);
    convert_x_kernel<<<((size_t)BDIM * KDIM) / (256 * 8), 256>>>(x);
    dim3 grid(NDIM / BN, BDIM / BM);          // (4, 64) = 256 CTAs
    binlin_gemm<<<grid, THREADS, SMEM_TOTAL>>>(out);
}